// round 15
// baseline (speedup 1.0000x reference)
#include <cuda_runtime.h>
#include <cuda_bf16.h>

#define NSP 8192
#define NR  2097152
#define NCTA 296
#define NTHR 640
#define RCHUNK 37          // 296 = 8 * 37

__device__ float g_partial[NCTA * NSP];   // 9.7 MB static scratch, overwritten each call

__device__ __forceinline__ float ex2_approx(float x) {
    float y;
    asm("ex2.approx.ftz.f32 %0, %1;" : "=f"(y) : "f"(x));
    return y;
}

__device__ __forceinline__ void red_shared_add(float* p, float v) {
    asm volatile("red.shared.add.f32 [%0], %1;"
                 :: "l"(__cvta_generic_to_shared(p)), "f"(v) : "memory");
}

struct Rxn {
    float a, b, g;
    int   t;
    int2  sp;
    int4  rw;
};

__device__ __forceinline__ Rxn load_rxn(
    int r,
    const float* __restrict__ alpha, const float* __restrict__ beta,
    const float* __restrict__ gamma, const int* __restrict__ rtype,
    const int2* __restrict__ rspec,  const int4* __restrict__ rows4)
{
    Rxn x;
    x.a = alpha[r]; x.b = beta[r]; x.g = gamma[r];
    x.t = rtype[r]; x.sp = rspec[r]; x.rw = rows4[r];
    return x;
}

__global__ __launch_bounds__(NTHR, 2)
void rates_scatter_kernel(
    const float* __restrict__ abund,
    const float* __restrict__ Tptr,
    const float* __restrict__ crptr,
    const float* __restrict__ fuvptr,
    const float* __restrict__ alpha,
    const float* __restrict__ beta,
    const float* __restrict__ gamma,
    const int*   __restrict__ rtype,
    const int2*  __restrict__ rspec,
    const int4*  __restrict__ rows4,
    float* __restrict__ out)
{
    extern __shared__ float smem[];
    float* acc = smem;          // [NSP] per-CTA accumulator (REDS targets)
    float* sab = smem + NSP;    // [NSP] staged abundances

    const int tid = threadIdx.x;
    for (int i = tid; i < NSP; i += NTHR) {
        acc[i] = 0.0f;
        sab[i] = abund[i];
    }
    // Zero poisoned output; reduce runs strictly after this kernel.
    if (blockIdx.x == 0)
        for (int i = tid; i < NSP; i += NTHR) out[i] = 0.0f;
    __syncthreads();

    const float T   = *Tptr;
    const float cr  = *crptr;
    const float fuv = *fuvptr;
    const float L2E = 1.4426950408889634f;           // log2(e)
    const float c1  = __log2f(T * (1.0f / 300.0f));  // log2(T/300)
    const float c2  = -L2E / T;                      // exp(-g/T) = exp2(g*c2)

    const int stride = gridDim.x * NTHR;
    int r = blockIdx.x * NTHR + tid;

    // Depth-2 software pipeline: loads for i+1 and i+2 stay in flight.
    Rxn cur, n1;
    if (r < NR)          cur = load_rxn(r,          alpha, beta, gamma, rtype, rspec, rows4);
    if (r + stride < NR) n1  = load_rxn(r + stride, alpha, beta, gamma, rtype, rspec, rows4);

    while (r < NR) {
        const int r2 = r + 2 * stride;

        Rxn n2;
        if (r2 < NR) n2 = load_rxn(r2, alpha, beta, gamma, rtype, rspec, rows4);

        {
            const float e  = (cur.t == 0) ? fmaf(cur.b, c1, cur.g * c2)
                                          : (-cur.g * L2E);
            const float ex = ex2_approx(e);
            float k;
            if (cur.t == 1)      k = cur.a * cr;
            else if (cur.t == 2) k = cur.a * fuv * ex;
            else                 k = cur.a * ex;

            k *= sab[cur.sp.x] * sab[cur.sp.y];

            red_shared_add(&acc[cur.rw.x], -k);   // no-return REDS
            red_shared_add(&acc[cur.rw.y], -k);
            red_shared_add(&acc[cur.rw.z],  k);
            red_shared_add(&acc[cur.rw.w],  k);
        }

        cur = n1;
        n1  = n2;
        r  += stride;
    }

    __syncthreads();
    // Plain coalesced STG flush.
    float* mine = g_partial + (size_t)blockIdx.x * NSP;
    for (int i = tid; i < NSP; i += NTHR)
        mine[i] = acc[i];
}

// Proven reduce: grid (32, 8), 256 threads; CTA (bx, by) sums rows
// [37*by, 37*(by+1)) for its 256-species chunk, one REDG per element.
__global__ __launch_bounds__(256, 8)
void reduce_kernel(float* __restrict__ out) {
    const int i  = blockIdx.x * blockDim.x + threadIdx.x;
    const int c0 = blockIdx.y * RCHUNK;
    const float* p = g_partial + (size_t)c0 * NSP + i;

    float s0 = 0.f, s1 = 0.f, s2 = 0.f, s3 = 0.f;
    #pragma unroll
    for (int c = 0; c < RCHUNK - 1; c += 4) {       // 36 rows, 4-deep MLP
        s0 += p[(size_t)c * NSP];
        s1 += p[(size_t)(c + 1) * NSP];
        s2 += p[(size_t)(c + 2) * NSP];
        s3 += p[(size_t)(c + 3) * NSP];
    }
    s0 += p[(size_t)(RCHUNK - 1) * NSP];            // row 36
    atomicAdd(&out[i], (s0 + s1) + (s2 + s3));      // no-return REDG, 8/address
}

extern "C" void kernel_launch(void* const* d_in, const int* in_sizes, int n_in,
                              void* d_out, int out_size) {
    const float* abund  = (const float*)d_in[0];
    const float* T      = (const float*)d_in[1];
    const float* crr    = (const float*)d_in[2];
    const float* fuvr   = (const float*)d_in[3];
    float* out = (float*)d_out;

    const int smem_bytes = 2 * NSP * sizeof(float);  // 64 KB
    cudaFuncSetAttribute(rates_scatter_kernel,
                         cudaFuncAttributeMaxDynamicSharedMemorySize, smem_bytes);

    rates_scatter_kernel<<<NCTA, NTHR, smem_bytes>>>(
        abund, T, crr, fuvr,
        (const float*)d_in[4], (const float*)d_in[5], (const float*)d_in[6],
        (const int*)d_in[7], (const int2*)d_in[8], (const int4*)d_in[9],
        out);

    reduce_kernel<<<dim3(NSP / 256, 8), 256>>>(out);
}

// round 16
// speedup vs baseline: 1.0808x; 1.0808x over previous
#include <cuda_runtime.h>
#include <cuda_bf16.h>

#define NSP 8192
#define NR  2097152
#define NCTA 148
#define NTHR 1024
#define RCHUNK 37          // 148 = 4 * 37

__device__ float g_partial[NCTA * NSP];   // 4.85 MB static scratch, overwritten each call

__device__ __forceinline__ float ex2_approx(float x) {
    float y;
    asm("ex2.approx.ftz.f32 %0, %1;" : "=f"(y) : "f"(x));
    return y;
}

__device__ __forceinline__ void red_shared_add(float* p, float v) {
    asm volatile("red.shared.add.f32 [%0], %1;"
                 :: "l"(__cvta_generic_to_shared(p)), "f"(v) : "memory");
}

struct Rxn {
    float a, b, g;
    int   t;
    int2  sp;
    int4  rw;
};

__device__ __forceinline__ Rxn load_rxn(
    int r,
    const float* __restrict__ alpha, const float* __restrict__ beta,
    const float* __restrict__ gamma, const int* __restrict__ rtype,
    const int2* __restrict__ rspec,  const int4* __restrict__ rows4)
{
    Rxn x;
    x.a = alpha[r]; x.b = beta[r]; x.g = gamma[r];
    x.t = rtype[r]; x.sp = rspec[r]; x.rw = rows4[r];
    return x;
}

__global__ __launch_bounds__(NTHR, 1)
void rates_scatter_kernel(
    const float* __restrict__ abund,
    const float* __restrict__ Tptr,
    const float* __restrict__ crptr,
    const float* __restrict__ fuvptr,
    const float* __restrict__ alpha,
    const float* __restrict__ beta,
    const float* __restrict__ gamma,
    const int*   __restrict__ rtype,
    const int2*  __restrict__ rspec,
    const int4*  __restrict__ rows4,
    float* __restrict__ out)
{
    extern __shared__ float smem[];
    float* acc = smem;          // [NSP] per-CTA accumulator (REDS targets)
    float* sab = smem + NSP;    // [NSP] staged abundances

    const int tid = threadIdx.x;
    for (int i = tid; i < NSP; i += NTHR) {
        acc[i] = 0.0f;
        sab[i] = abund[i];
    }
    // Zero poisoned output; reduce runs strictly after this kernel.
    if (blockIdx.x == 0)
        for (int i = tid; i < NSP; i += NTHR) out[i] = 0.0f;
    __syncthreads();

    const float T   = *Tptr;
    const float cr  = *crptr;
    const float fuv = *fuvptr;
    const float L2E = 1.4426950408889634f;           // log2(e)
    const float c1  = __log2f(T * (1.0f / 300.0f));  // log2(T/300)
    const float c2  = -L2E / T;                      // exp(-g/T) = exp2(g*c2)

    const int stride = NCTA * NTHR;                  // 151552
    int r = blockIdx.x * NTHR + tid;

    // Depth-2 software pipeline: loads for i+1 and i+2 stay in flight.
    Rxn cur, n1;
    if (r < NR)          cur = load_rxn(r,          alpha, beta, gamma, rtype, rspec, rows4);
    if (r + stride < NR) n1  = load_rxn(r + stride, alpha, beta, gamma, rtype, rspec, rows4);

    while (r < NR) {
        const int r2 = r + 2 * stride;

        Rxn n2;
        if (r2 < NR) n2 = load_rxn(r2, alpha, beta, gamma, rtype, rspec, rows4);

        {
            const float e  = (cur.t == 0) ? fmaf(cur.b, c1, cur.g * c2)
                                          : (-cur.g * L2E);
            const float ex = ex2_approx(e);
            float k;
            if (cur.t == 1)      k = cur.a * cr;
            else if (cur.t == 2) k = cur.a * fuv * ex;
            else                 k = cur.a * ex;

            k *= sab[cur.sp.x] * sab[cur.sp.y];

            red_shared_add(&acc[cur.rw.x], -k);   // no-return REDS
            red_shared_add(&acc[cur.rw.y], -k);
            red_shared_add(&acc[cur.rw.z],  k);
            red_shared_add(&acc[cur.rw.w],  k);
        }

        cur = n1;
        n1  = n2;
        r  += stride;
    }

    __syncthreads();
    // Plain coalesced STG flush (now only 148 partials).
    float* mine = g_partial + (size_t)blockIdx.x * NSP;
    for (int i = tid; i < NSP; i += NTHR)
        mine[i] = acc[i];
}

// Reduce over 148 partials: grid (32, 4), 256 threads; CTA (bx, by) sums rows
// [37*by, 37*(by+1)) for its 256-species chunk, one REDG per element (4/address).
__global__ __launch_bounds__(256, 8)
void reduce_kernel(float* __restrict__ out) {
    const int i  = blockIdx.x * blockDim.x + threadIdx.x;
    const int c0 = blockIdx.y * RCHUNK;
    const float* p = g_partial + (size_t)c0 * NSP + i;

    float s0 = 0.f, s1 = 0.f, s2 = 0.f, s3 = 0.f;
    #pragma unroll
    for (int c = 0; c < RCHUNK - 1; c += 4) {       // 36 rows, 4-deep MLP
        s0 += p[(size_t)c * NSP];
        s1 += p[(size_t)(c + 1) * NSP];
        s2 += p[(size_t)(c + 2) * NSP];
        s3 += p[(size_t)(c + 3) * NSP];
    }
    s0 += p[(size_t)(RCHUNK - 1) * NSP];            // row 36
    atomicAdd(&out[i], (s0 + s1) + (s2 + s3));      // no-return REDG, 4/address
}

extern "C" void kernel_launch(void* const* d_in, const int* in_sizes, int n_in,
                              void* d_out, int out_size) {
    const float* abund  = (const float*)d_in[0];
    const float* T      = (const float*)d_in[1];
    const float* crr    = (const float*)d_in[2];
    const float* fuvr   = (const float*)d_in[3];
    float* out = (float*)d_out;

    const int smem_bytes = 2 * NSP * sizeof(float);  // 64 KB
    cudaFuncSetAttribute(rates_scatter_kernel,
                         cudaFuncAttributeMaxDynamicSharedMemorySize, smem_bytes);

    rates_scatter_kernel<<<NCTA, NTHR, smem_bytes>>>(
        abund, T, crr, fuvr,
        (const float*)d_in[4], (const float*)d_in[5], (const float*)d_in[6],
        (const int*)d_in[7], (const int2*)d_in[8], (const int4*)d_in[9],
        out);

    reduce_kernel<<<dim3(NSP / 256, 4), 256>>>(out);
}